// round 7
// baseline (speedup 1.0000x reference)
#include <cuda_runtime.h>
#include <cstdint>

// Problem: B=32, T=256, D=64.
// real, imag: [B, T, D] float32.
// out: [2, T, B, D, D] float32.
//   out_real[t,b,p,q] = r_p*r_q + i_p*i_q
//   out_imag[t,b,p,q] = i_p*r_q - r_p*i_q
// where r = real[b, t, :], i = imag[b, t, :].

#define PB 32
#define PT 256
#define PD 64
#define TILE (PD * PD)            // 4096 floats = 16KiB per (t,b) per component
#define NTB  (PT * PB)            // 8192 tiles per component
#define IMAG_OFF ((size_t)NTB * TILE)

__global__ __launch_bounds__(256, 8)
void qouterc_kernel(const float* __restrict__ real,
                    const float* __restrict__ imag,
                    float* __restrict__ out)
{
    // grid = 2 * NTB. First NTB CTAs write the real half, next NTB the imag
    // half. Each CTA emits exactly ONE contiguous 16KiB output stream via a
    // single TMA bulk store (sequential burst order to DRAM, vs 32
    // interleaved warp STGs).
    const int bid  = blockIdx.x;
    const int comp = bid >> 13;         // 0 = real part, 1 = imag part
    const int tb   = bid & (NTB - 1);   // tb = t*B + b (matches out layout)
    const int t    = tb >> 5;           // / 32
    const int b    = tb & 31;

    __shared__ __align__(16)  float rs[PD];
    __shared__ __align__(16)  float is[PD];
    __shared__ __align__(128) float tile[TILE];   // 16KiB staging buffer

    const int tid = threadIdx.x;

    // Input layout [B, T, D]: element (b, t, d) at b*T*D + t*D + d
    const size_t in_base = (size_t)b * (PT * PD) + (size_t)t * PD;
    if (tid < PD)
        rs[tid] = real[in_base + tid];
    else if (tid < 2 * PD)
        is[tid - PD] = imag[in_base + (tid - PD)];
    __syncthreads();

    // Mapping: n4 = j*256 + tid, p = j*16 + (tid>>4), q = (tid&15)<<2
    // (q is j-invariant -> one LDS.128 pair reused across all 4 iterations).
    const int q  = (tid & 15) << 2;
    const int p0 = tid >> 4;

    const float4 rq4 = *reinterpret_cast<const float4*>(&rs[q]);
    const float4 iq4 = *reinterpret_cast<const float4*>(&is[q]);

    #pragma unroll
    for (int j = 0; j < 4; ++j) {
        const int p  = j * 16 + p0;
        const int n4 = j * 256 + tid;

        const float rp = rs[p];
        const float ip = is[p];

        float4 v;
        if (comp == 0) {
            v.x = rp * rq4.x + ip * iq4.x;
            v.y = rp * rq4.y + ip * iq4.y;
            v.z = rp * rq4.z + ip * iq4.z;
            v.w = rp * rq4.w + ip * iq4.w;
        } else {
            v.x = ip * rq4.x - rp * iq4.x;
            v.y = ip * rq4.y - rp * iq4.y;
            v.z = ip * rq4.z - rp * iq4.z;
            v.w = ip * rq4.w - rp * iq4.w;
        }
        // STS.128, consecutive tids -> consecutive 16B -> conflict-free.
        reinterpret_cast<float4*>(tile)[n4] = v;
    }
    __syncthreads();

    // One bulk async store: smem tile -> contiguous 16KiB global run.
    if (tid == 0) {
        float* dst = out + (size_t)comp * IMAG_OFF + (size_t)tb * TILE;
        uint32_t saddr;
        asm("{ .reg .u64 t0; cvta.to.shared.u64 t0, %1; cvt.u32.u64 %0, t0; }"
            : "=r"(saddr) : "l"(tile));
        asm volatile("fence.proxy.async.shared::cta;" ::: "memory");
        asm volatile(
            "cp.async.bulk.global.shared::cta.bulk_group [%0], [%1], %2;"
            :: "l"(dst), "r"(saddr), "r"((int)(TILE * sizeof(float)))
            : "memory");
        asm volatile("cp.async.bulk.commit_group;" ::: "memory");
        asm volatile("cp.async.bulk.wait_group 0;" ::: "memory");
    }
}

extern "C" void kernel_launch(void* const* d_in, const int* in_sizes, int n_in,
                              void* d_out, int out_size)
{
    const float* real = (const float*)d_in[0];
    const float* imag = (const float*)d_in[1];
    float* out = (float*)d_out;

    // 2 components x 8192 (t,b) tiles; 256 threads each.
    qouterc_kernel<<<2 * NTB, 256>>>(real, imag, out);
}

// round 9
// speedup vs baseline: 1.2281x; 1.2281x over previous
#include <cuda_runtime.h>

// Problem: B=32, T=256, D=64.
// real, imag: [B, T, D] float32.
// out: [2, T, B, D, D] float32.
//   out_real[t,b,p,q] = r_p*r_q + i_p*i_q
//   out_imag[t,b,p,q] = i_p*r_q - r_p*i_q
// where r = real[b, t, :], i = imag[b, t, :].

#define PB 32
#define PT 256
#define PD 64
#define TILE (PD * PD)            // 4096 floats per (t,b) per component
#define NTB  (PT * PB)            // 8192 tiles per component
#define IMAG_OFF ((size_t)NTB * TILE)

__global__ __launch_bounds__(256, 8)
void qouterc_kernel(const float* __restrict__ real,
                    const float* __restrict__ imag,
                    float* __restrict__ out)
{
    // grid = 2 * NTB. First NTB CTAs write the real half, next NTB the imag
    // half. Each CTA writes exactly ONE contiguous 16KiB output stream.
    const int bid  = blockIdx.x;
    const int comp = bid >> 13;         // 0 = real part, 1 = imag part
    const int tb   = bid & (NTB - 1);   // tb = t*B + b (matches out layout)
    const int t    = tb >> 5;           // / 32
    const int b    = tb & 31;

    __shared__ __align__(16) float rs[PD];
    __shared__ __align__(16) float is[PD];

    const int tid = threadIdx.x;

    // Input layout [B, T, D]: element (b, t, d) at b*T*D + t*D + d
    const size_t in_base = (size_t)b * (PT * PD) + (size_t)t * PD;
    if (tid < PD)
        rs[tid] = real[in_base + tid];
    else if (tid < 2 * PD)
        is[tid - PD] = imag[in_base + (tid - PD)];
    __syncthreads();

    // Mapping: n4 = j*256 + tid, p = n4>>4 = j*16 + (tid>>4),
    //          q = (n4&15)<<2 = (tid&15)<<2  -> q is j-INVARIANT.
    // The 4 q-values are loaded ONCE as an LDS.128 pair and reused across
    // all 4 j iterations.
    const int q  = (tid & 15) << 2;
    const int p0 = tid >> 4;

    const float4 rq4 = *reinterpret_cast<const float4*>(&rs[q]);
    const float4 iq4 = *reinterpret_cast<const float4*>(&is[q]);

    float* out_t = out + (size_t)comp * IMAG_OFF + (size_t)tb * TILE;

    #pragma unroll
    for (int j = 0; j < 4; ++j) {
        const int p  = j * 16 + p0;          // row
        const int n4 = j * 256 + tid;        // float4 index, 0..1023

        const float rp = rs[p];              // broadcast LDS (conflict-free)
        const float ip = is[p];

        float4 v;
        if (comp == 0) {
            v.x = rp * rq4.x + ip * iq4.x;
            v.y = rp * rq4.y + ip * iq4.y;
            v.z = rp * rq4.z + ip * iq4.z;
            v.w = rp * rq4.w + ip * iq4.w;
        } else {
            v.x = ip * rq4.x - rp * iq4.x;
            v.y = ip * rq4.y - rp * iq4.y;
            v.z = ip * rq4.z - rp * iq4.z;
            v.w = ip * rq4.w - rp * iq4.w;
        }

        // DEFAULT cache policy (no .cs): let L2 accumulate large dirty
        // regions and evict in address-sorted batches -> better DRAM write
        // scheduling than eager evict-first fragments.
        reinterpret_cast<float4*>(out_t)[n4] = v;
    }
}

extern "C" void kernel_launch(void* const* d_in, const int* in_sizes, int n_in,
                              void* d_out, int out_size)
{
    const float* real = (const float*)d_in[0];
    const float* imag = (const float*)d_in[1];
    float* out = (float*)d_out;

    // 2 components x 8192 (t,b) tiles; 256 threads each.
    qouterc_kernel<<<2 * NTB, 256>>>(real, imag, out);
}

// round 10
// speedup vs baseline: 1.4257x; 1.1608x over previous
#include <cuda_runtime.h>

// Problem: B=32, T=256, D=64.
// real, imag: [B, T, D] float32.
// out: [2, T, B, D, D] float32.
//   out_real[t,b,p,q] = r_p*r_q + i_p*i_q
//   out_imag[t,b,p,q] = i_p*r_q - r_p*i_q
// where r = real[b, t, :], i = imag[b, t, :].
//
// Design (settled over R1-R8):
//  - Pure HBM-write-bound: 256MiB compulsory output, 0.75 flop/byte.
//  - One CTA per (component, t, b): each CTA emits ONE contiguous 16KiB
//    write stream (best DRAM locality among all variants tested).
//  - __stcs (evict-first): keeps the write-once stream from thrashing L2
//    and evicting the L2-resident inputs across graph replays (default
//    policy cost +5.7us; measured R8).
//  - q-index is j-invariant -> rq/iq hoisted as one LDS.128 pair.
//  - 23 regs, occ ~90%: maximizes store-level parallelism (v8 stores cost
//    occupancy and regressed; TMA bulk store serialized and regressed).

#define PB 32
#define PT 256
#define PD 64
#define TILE (PD * PD)            // 4096 floats per (t,b) per component
#define NTB  (PT * PB)            // 8192 tiles per component
#define IMAG_OFF ((size_t)NTB * TILE)

__global__ __launch_bounds__(256, 8)
void qouterc_kernel(const float* __restrict__ real,
                    const float* __restrict__ imag,
                    float* __restrict__ out)
{
    const int bid  = blockIdx.x;
    const int comp = bid >> 13;         // 0 = real part, 1 = imag part
    const int tb   = bid & (NTB - 1);   // tb = t*B + b (matches out layout)
    const int t    = tb >> 5;           // / 32
    const int b    = tb & 31;

    __shared__ __align__(16) float rs[PD];
    __shared__ __align__(16) float is[PD];

    const int tid = threadIdx.x;

    // Input layout [B, T, D]: element (b, t, d) at b*T*D + t*D + d
    const size_t in_base = (size_t)b * (PT * PD) + (size_t)t * PD;
    if (tid < PD)
        rs[tid] = real[in_base + tid];
    else if (tid < 2 * PD)
        is[tid - PD] = imag[in_base + (tid - PD)];
    __syncthreads();

    // Mapping: n4 = j*256 + tid, p = n4>>4 = j*16 + (tid>>4),
    //          q = (n4&15)<<2 = (tid&15)<<2  -> q is j-INVARIANT.
    const int q  = (tid & 15) << 2;
    const int p0 = tid >> 4;

    const float4 rq4 = *reinterpret_cast<const float4*>(&rs[q]);
    const float4 iq4 = *reinterpret_cast<const float4*>(&is[q]);

    float* out_t = out + (size_t)comp * IMAG_OFF + (size_t)tb * TILE;

    #pragma unroll
    for (int j = 0; j < 4; ++j) {
        const int p  = j * 16 + p0;          // row
        const int n4 = j * 256 + tid;        // float4 index, 0..1023

        const float rp = rs[p];              // broadcast LDS (conflict-free)
        const float ip = is[p];

        float4 v;
        if (comp == 0) {
            v.x = rp * rq4.x + ip * iq4.x;
            v.y = rp * rq4.y + ip * iq4.y;
            v.z = rp * rq4.z + ip * iq4.z;
            v.w = rp * rq4.w + ip * iq4.w;
        } else {
            v.x = ip * rq4.x - rp * iq4.x;
            v.y = ip * rq4.y - rp * iq4.y;
            v.z = ip * rq4.z - rp * iq4.z;
            v.w = ip * rq4.w - rp * iq4.w;
        }

        // Streaming store: write-once output, evict-first in L2.
        __stcs(reinterpret_cast<float4*>(out_t) + n4, v);
    }
}

extern "C" void kernel_launch(void* const* d_in, const int* in_sizes, int n_in,
                              void* d_out, int out_size)
{
    const float* real = (const float*)d_in[0];
    const float* imag = (const float*)d_in[1];
    float* out = (float*)d_out;

    // 2 components x 8192 (t,b) tiles; 256 threads each.
    qouterc_kernel<<<2 * NTB, 256>>>(real, imag, out);
}